// round 2
// baseline (speedup 1.0000x reference)
#include <cuda_runtime.h>
#include <math.h>

// RNNLayer_73074573574765: delayed RNN
//   B=64, S=512, I=1024, H=1024, DELAY=4
// Phase 1: pre[m,h] = X . Wih^T + bih + bhh  (one big GEMM, FFMA2)
// Phase 2: 128 sequential groups of 4 independent timesteps (FFMA2 GEMM + tanh)
// Phase 3: h_final copy.

namespace {
constexpr int Bz = 64;
constexpr int Sz = 512;
constexpr int Iz = 1024;
constexpr int Hz = 1024;
constexpr int DZ = 4;
}  // namespace

typedef unsigned long long u64;

__device__ float g_pre[(size_t)Bz * Sz * Hz];

// Packed fp32x2 FMA (Blackwell; ptxas never auto-fuses — PTX only).
__device__ __forceinline__ u64 ffma2(u64 a, u64 b, u64 c) {
  u64 d;
  asm("fma.rn.f32x2 %0, %1, %2, %3;" : "=l"(d) : "l"(a), "l"(b), "l"(c));
  return d;
}

__device__ __forceinline__ float2 unpack2(u64 v) {
  float2 f;
  asm("mov.b64 {%0, %1}, %2;" : "=f"(f.x), "=f"(f.y) : "l"(v));
  return f;
}

// ---------------------------------------------------------------------------
// Phase 1: C[m,n] = sum_k X[m,k]*Wih[n,k] + bih[n] + bhh[n]
// M=32768, N=1024, K=1024. BM=BN=128, BK=8, 256 thr, 8x8 per thread.
// A stored duplicated ({a,a}) in SMEM so FFMA2 needs no lane-dup MOVs.
// ---------------------------------------------------------------------------
__global__ __launch_bounds__(256, 2) void pre_gemm_kernel(
    const float* __restrict__ X, const float* __restrict__ Wih,
    const float* __restrict__ bih, const float* __restrict__ bhh) {
  __shared__ float2 Asd[2][8][128];  // dup pairs: 16 KB
  __shared__ float Bsf[2][8][128];   // 8 KB

  const int tid = threadIdx.x;
  const int bm = blockIdx.y;
  const int bn = blockIdx.x;

  // loaders: 256 threads cover 128 rows x 8 k as one float4 each
  const int lrow = tid >> 1;
  const int lcol = (tid & 1) << 2;
  const float* Ag = X + (size_t)(bm * 128 + lrow) * Iz + lcol;
  const float* Bg = Wih + (size_t)(bn * 128 + lrow) * Iz + lcol;

  const int tr = tid >> 4;  // 0..15 -> rows tr*8..+7
  const int tc = tid & 15;  // 0..15 -> cols tc*8..+7

  u64 acc[8][4];
#pragma unroll
  for (int i = 0; i < 8; i++)
#pragma unroll
    for (int j = 0; j < 4; j++) acc[i][j] = 0ull;  // packed {+0,+0}

  float4 pa = *reinterpret_cast<const float4*>(Ag);
  float4 pb = *reinterpret_cast<const float4*>(Bg);
  {
    float av[4] = {pa.x, pa.y, pa.z, pa.w};
    float bv[4] = {pb.x, pb.y, pb.z, pb.w};
#pragma unroll
    for (int i = 0; i < 4; i++) {
      Asd[0][lcol + i][lrow] = make_float2(av[i], av[i]);
      Bsf[0][lcol + i][lrow] = bv[i];
    }
  }
  __syncthreads();

  const int NIT = Iz / 8;  // 128
  for (int it = 0; it < NIT; ++it) {
    const int cur = it & 1;
    if (it + 1 < NIT) {
      pa = *reinterpret_cast<const float4*>(Ag + (it + 1) * 8);
      pb = *reinterpret_cast<const float4*>(Bg + (it + 1) * 8);
    }
#pragma unroll
    for (int k = 0; k < 8; k++) {
      const u64* ap = reinterpret_cast<const u64*>(&Asd[cur][k][tr * 8]);
      const u64* bp = reinterpret_cast<const u64*>(&Bsf[cur][k][tc * 8]);
      u64 a[8], b[4];
#pragma unroll
      for (int i = 0; i < 8; i++) a[i] = ap[i];
#pragma unroll
      for (int j = 0; j < 4; j++) b[j] = bp[j];
#pragma unroll
      for (int i = 0; i < 8; i++)
#pragma unroll
        for (int j = 0; j < 4; j++) acc[i][j] = ffma2(a[i], b[j], acc[i][j]);
    }
    if (it + 1 < NIT) {
      const int nxt = cur ^ 1;
      float av[4] = {pa.x, pa.y, pa.z, pa.w};
      float bv[4] = {pb.x, pb.y, pb.z, pb.w};
#pragma unroll
      for (int i = 0; i < 4; i++) {
        Asd[nxt][lcol + i][lrow] = make_float2(av[i], av[i]);
        Bsf[nxt][lcol + i][lrow] = bv[i];
      }
    }
    __syncthreads();
  }

  float bias[8];
#pragma unroll
  for (int j = 0; j < 8; j++) {
    int n = bn * 128 + tc * 8 + j;
    bias[j] = bih[n] + bhh[n];
  }

#pragma unroll
  for (int i = 0; i < 8; i++) {
    size_t row = (size_t)(bm * 128 + tr * 8 + i) * Hz;
    size_t col = (size_t)bn * 128 + tc * 8;
#pragma unroll
    for (int jp = 0; jp < 4; jp += 2) {
      float2 v0 = unpack2(acc[i][jp]);
      float2 v1 = unpack2(acc[i][jp + 1]);
      float4 v;
      v.x = v0.x + bias[jp * 2 + 0];
      v.y = v0.y + bias[jp * 2 + 1];
      v.z = v1.x + bias[jp * 2 + 2];
      v.w = v1.y + bias[jp * 2 + 3];
      *reinterpret_cast<float4*>(&g_pre[row + col + jp * 2]) = v;
    }
  }
}

// ---------------------------------------------------------------------------
// Phase 2: one group g = 4 independent timesteps. Rows m = d*64 + b (0..255).
// out[b,4g+d,n] = tanh(pre + hprev . Whh^T)
// BM=32, BN=64, BK=16, 256 thr, 2x4 per thread via FFMA2. Grid 16x8 = 128.
// Register-prefetch double-buffered SMEM; A dup-stored.
// ---------------------------------------------------------------------------
__global__ __launch_bounds__(256) void rnn_step_kernel(
    const float* __restrict__ hs, const float* __restrict__ Whh,
    float* __restrict__ out, int gstep) {
  __shared__ float2 Asd[2][16][32];  // dup pairs: 8 KB
  __shared__ float Bsf[2][16][64];   // 8 KB

  const int tid = threadIdx.x;
  const int bn = blockIdx.x;  // 0..15 over N
  const int bm = blockIdx.y;  // 0..7  over M=256

  // A loader: 32 rows x 16 k, one float2 each
  const int arow = tid >> 3;      // 0..31
  const int ak = (tid & 7) << 1;  // 0..14
  const int m = bm * 32 + arow;
  const int dA = m >> 6;
  const int bA = m & 63;
  const float* hrow;
  if (gstep == 0)
    hrow = hs + (size_t)m * Hz;  // hidden_state [4,64,H] flattens to [m,H]
  else
    hrow = out + ((size_t)bA * Sz + (4 * gstep + dA - 4)) * Hz;
  hrow += ak;

  // B loader: 64 rows x 16 k, one float4 each
  const int brow = tid >> 2;      // 0..63
  const int bk = (tid & 3) << 2;  // 0,4,8,12
  const float* wrow = Whh + (size_t)(bn * 64 + brow) * Hz + bk;

  const int tr = tid >> 4;  // 0..15 -> rows tr*2, tr*2+1
  const int tc = tid & 15;  // 0..15 -> cols tc*4..+3

  u64 acc[2][2] = {{0ull, 0ull}, {0ull, 0ull}};

  float2 pa = *reinterpret_cast<const float2*>(hrow);
  float4 pb = *reinterpret_cast<const float4*>(wrow);
  Asd[0][ak + 0][arow] = make_float2(pa.x, pa.x);
  Asd[0][ak + 1][arow] = make_float2(pa.y, pa.y);
  Bsf[0][bk + 0][brow] = pb.x;
  Bsf[0][bk + 1][brow] = pb.y;
  Bsf[0][bk + 2][brow] = pb.z;
  Bsf[0][bk + 3][brow] = pb.w;
  __syncthreads();

  const int NIT = Hz / 16;  // 64
  for (int it = 0; it < NIT; ++it) {
    const int cur = it & 1;
    if (it + 1 < NIT) {
      pa = *reinterpret_cast<const float2*>(hrow + (it + 1) * 16);
      pb = *reinterpret_cast<const float4*>(wrow + (it + 1) * 16);
    }
#pragma unroll
    for (int k = 0; k < 16; k++) {
      const u64* ap = reinterpret_cast<const u64*>(&Asd[cur][k][tr * 2]);
      const u64* bp = reinterpret_cast<const u64*>(&Bsf[cur][k][tc * 4]);
      u64 a0 = ap[0], a1 = ap[1];
      u64 b0 = bp[0], b1 = bp[1];
      acc[0][0] = ffma2(a0, b0, acc[0][0]);
      acc[0][1] = ffma2(a0, b1, acc[0][1]);
      acc[1][0] = ffma2(a1, b0, acc[1][0]);
      acc[1][1] = ffma2(a1, b1, acc[1][1]);
    }
    if (it + 1 < NIT) {
      const int nxt = cur ^ 1;
      Asd[nxt][ak + 0][arow] = make_float2(pa.x, pa.x);
      Asd[nxt][ak + 1][arow] = make_float2(pa.y, pa.y);
      Bsf[nxt][bk + 0][brow] = pb.x;
      Bsf[nxt][bk + 1][brow] = pb.y;
      Bsf[nxt][bk + 2][brow] = pb.z;
      Bsf[nxt][bk + 3][brow] = pb.w;
    }
    __syncthreads();
  }

#pragma unroll
  for (int i = 0; i < 2; i++) {
    const int mm = bm * 32 + tr * 2 + i;
    const int dd = mm >> 6;
    const int bb = mm & 63;
    const int t = 4 * gstep + dd;
    const size_t base = ((size_t)bb * Sz + t) * Hz + (size_t)bn * 64 + tc * 4;
    float2 v0 = unpack2(acc[i][0]);
    float2 v1 = unpack2(acc[i][1]);
    float4 pv = *reinterpret_cast<const float4*>(&g_pre[base]);
    float4 ov;
    ov.x = tanhf(pv.x + v0.x);
    ov.y = tanhf(pv.y + v0.y);
    ov.z = tanhf(pv.z + v1.x);
    ov.w = tanhf(pv.w + v1.y);
    *reinterpret_cast<float4*>(&out[base]) = ov;
  }
}

// ---------------------------------------------------------------------------
// Phase 3: h_final[d,b,h] = out[b, S-4+d, h]
// ---------------------------------------------------------------------------
__global__ void final_state_kernel(const float* __restrict__ out,
                                   float* __restrict__ hf) {
  int idx = blockIdx.x * 256 + threadIdx.x;  // DZ*Bz*Hz = 262144
  int h = idx & (Hz - 1);
  int bd = idx >> 10;
  int b = bd & (Bz - 1);
  int d = bd >> 6;
  hf[idx] = out[((size_t)b * Sz + (Sz - DZ + d)) * Hz + h];
}

extern "C" void kernel_launch(void* const* d_in, const int* in_sizes, int n_in,
                              void* d_out, int out_size) {
  (void)in_sizes;
  (void)n_in;
  (void)out_size;
  const float* X = (const float*)d_in[0];    // [B,S,I]
  const float* hs = (const float*)d_in[1];   // [4,B,H]
  const float* Wih = (const float*)d_in[2];  // [H,I]
  const float* Whh = (const float*)d_in[3];  // [H,H]
  const float* bih = (const float*)d_in[4];  // [H]
  const float* bhh = (const float*)d_in[5];  // [H]

  float* out = (float*)d_out;              // [B,S,H]
  float* hf = out + (size_t)Bz * Sz * Hz;  // [4,B,H]

  pre_gemm_kernel<<<dim3(Hz / 128, (Bz * Sz) / 128), 256>>>(X, Wih, bih, bhh);

  for (int g = 0; g < Sz / DZ; ++g) {
    rnn_step_kernel<<<dim3(Hz / 64, 256 / 32), 256>>>(hs, Whh, out, g);
  }

  final_state_kernel<<<(DZ * Bz * Hz) / 256, 256>>>(out, hf);
}

// round 3
// speedup vs baseline: 1.6860x; 1.6860x over previous
#include <cuda_runtime.h>
#include <math.h>

// RNNLayer_73074573574765: delayed RNN. B=64,S=512,I=H=1024,DELAY=4.
// Phase 1: pre = X.Wih^T + bih + bhh (separate GEMM kernel, proven R1 code)
// Phase 2: ONE persistent kernel; 128 groups of 4 independent steps,
//          software grid barrier between groups.
// Phase 3: h_final copy.

namespace {
constexpr int Bz = 64;
constexpr int Sz = 512;
constexpr int Iz = 1024;
constexpr int Hz = 1024;
constexpr int DZ = 4;
constexpr int NBLK = 128;   // persistent blocks (<=148 SMs, all co-resident)
constexpr int BM = 32;      // M tile   (8 blocks cover M=256)
constexpr int BN = 64;      // N tile   (16 blocks cover N=1024)
constexpr int BK = 32;      // K chunk
constexpr int NGROUP = Sz / DZ;  // 128
}  // namespace

typedef unsigned long long u64;

__device__ float g_pre[(size_t)Bz * Sz * Hz];
__device__ unsigned g_cnt;  // zero-init; self-cleaning
__device__ unsigned g_gen;  // monotonically increasing; equality-compared

// Packed fp32x2 FMA (PTX-only on Blackwell).
__device__ __forceinline__ u64 ffma2(u64 a, u64 b, u64 c) {
  u64 d;
  asm("fma.rn.f32x2 %0, %1, %2, %3;" : "=l"(d) : "l"(a), "l"(b), "l"(c));
  return d;
}
__device__ __forceinline__ float2 unpack2(u64 v) {
  float2 f;
  asm("mov.b64 {%0, %1}, %2;" : "=f"(f.x), "=f"(f.y) : "l"(v));
  return f;
}

// Sense-style grid barrier across NBLK co-resident blocks.
__device__ __forceinline__ void grid_barrier() {
  __syncthreads();
  if (threadIdx.x == 0) {
    unsigned gen = *(volatile unsigned*)&g_gen;
    __threadfence();  // make this block's STGs visible before arrival
    if (atomicAdd(&g_cnt, 1) == NBLK - 1) {
      g_cnt = 0;
      __threadfence();
      atomicAdd(&g_gen, 1);
    } else {
      while (*(volatile unsigned*)&g_gen == gen) __nanosleep(32);
    }
    __threadfence();  // acquire side (flushes L1D on sm_103a)
  }
  __syncthreads();
}

// ---------------------------------------------------------------------------
// Phase 2 persistent kernel.
// Block tile 32x64; 512 threads; warp grid 4(m)x4(n); warp tile 8m x 16n;
// thread tile 2m x 2n via 2 FFMA2/k.  A dup-stored as float2 pairs, k-major.
// ---------------------------------------------------------------------------
__global__ __launch_bounds__(512, 1) void rnn_persistent(
    const float* __restrict__ hs, const float* __restrict__ Whh,
    float* __restrict__ out) {
  // Ad[k][m] = {A[m,k], A[m,k]}  (row 34 float2 = 272B, keeps 16B align + no bank conflicts)
  __shared__ __align__(16) float2 Ad[2][BK][BM + 2];
  // Bp[k][pn] = {W[2pn,k], W[2pn+1,k]}  (row 33 float2)
  __shared__ float2 Bp[2][BK][BN / 2 + 1];

  const int tid = threadIdx.x;
  const int bmi = blockIdx.x >> 4;  // 0..7
  const int bni = blockIdx.x & 15;  // 0..15

  // A loader: row am (0..31), k-pair akq (0..15)
  const int am = tid >> 4;
  const int akq = tid & 15;
  const int m_abs_l = bmi * BM + am;        // 0..255
  const int dl = m_abs_l >> 6;              // step-in-group
  const int bl = m_abs_l & 63;              // batch
  // B loader: row bn (0..63), k-quad bkq (0..7)
  const int bn = tid >> 3;
  const int bkq = tid & 7;
  const float* wrow = Whh + (size_t)(bni * BN + bn) * Hz + 4 * bkq;

  // compute mapping
  const int w = tid >> 5;
  const int lane = tid & 31;
  const int wm = w >> 2, wn = w & 3;
  const int pm = wm * 4 + (lane >> 3);  // m-pair 0..15
  const int pn = wn * 8 + (lane & 7);   // n-pair 0..31

  for (int g = 0; g < NGROUP; ++g) {
    const float* hrow =
        (g == 0)
            ? hs + (size_t)m_abs_l * Hz + 2 * akq
            : out + ((size_t)bl * Sz + (4 * g + dl - 4)) * Hz + 2 * akq;

    u64 acc0 = 0ull, acc1 = 0ull;

    // prime chunk 0
    float2 pa = *reinterpret_cast<const float2*>(hrow);
    float4 pb = *reinterpret_cast<const float4*>(wrow);
    Ad[0][2 * akq + 0][am] = make_float2(pa.x, pa.x);
    Ad[0][2 * akq + 1][am] = make_float2(pa.y, pa.y);
    reinterpret_cast<float*>(&Bp[0][4 * bkq + 0][0])[bn] = pb.x;
    reinterpret_cast<float*>(&Bp[0][4 * bkq + 1][0])[bn] = pb.y;
    reinterpret_cast<float*>(&Bp[0][4 * bkq + 2][0])[bn] = pb.z;
    reinterpret_cast<float*>(&Bp[0][4 * bkq + 3][0])[bn] = pb.w;
    __syncthreads();

    const int NC = Hz / BK;  // 32
    for (int c = 0; c < NC; ++c) {
      const int cur = c & 1;
      if (c + 1 < NC) {
        pa = *reinterpret_cast<const float2*>(hrow + (c + 1) * BK);
        pb = *reinterpret_cast<const float4*>(wrow + (c + 1) * BK);
      }
#pragma unroll
      for (int k = 0; k < BK; ++k) {
        ulonglong2 av =
            *reinterpret_cast<const ulonglong2*>(&Ad[cur][k][2 * pm]);
        u64 bv = *reinterpret_cast<const u64*>(&Bp[cur][k][pn]);
        acc0 = ffma2(av.x, bv, acc0);
        acc1 = ffma2(av.y, bv, acc1);
      }
      if (c + 1 < NC) {
        const int nxt = cur ^ 1;
        Ad[nxt][2 * akq + 0][am] = make_float2(pa.x, pa.x);
        Ad[nxt][2 * akq + 1][am] = make_float2(pa.y, pa.y);
        reinterpret_cast<float*>(&Bp[nxt][4 * bkq + 0][0])[bn] = pb.x;
        reinterpret_cast<float*>(&Bp[nxt][4 * bkq + 1][0])[bn] = pb.y;
        reinterpret_cast<float*>(&Bp[nxt][4 * bkq + 2][0])[bn] = pb.z;
        reinterpret_cast<float*>(&Bp[nxt][4 * bkq + 3][0])[bn] = pb.w;
      }
      __syncthreads();
    }

    // epilogue: tanh(pre + acc) -> out
    {
      const int n_off = bni * BN + 2 * pn;
#pragma unroll
      for (int i = 0; i < 2; ++i) {
        const int m_abs = bmi * BM + 2 * pm + i;
        const int d = m_abs >> 6;
        const int b = m_abs & 63;
        const size_t base = ((size_t)b * Sz + (4 * g + d)) * Hz + n_off;
        float2 pv = *reinterpret_cast<const float2*>(&g_pre[base]);
        float2 ac = unpack2(i == 0 ? acc0 : acc1);
        float2 ov =
            make_float2(tanhf(pv.x + ac.x), tanhf(pv.y + ac.y));
        *reinterpret_cast<float2*>(&out[base]) = ov;
      }
    }
    grid_barrier();
  }
}

// ---------------------------------------------------------------------------
// Phase 1 (unchanged proven R1 code): pre = X.Wih^T + bih + bhh
// ---------------------------------------------------------------------------
__global__ __launch_bounds__(256, 2) void pre_gemm_kernel(
    const float* __restrict__ X, const float* __restrict__ Wih,
    const float* __restrict__ bih, const float* __restrict__ bhh) {
  __shared__ float As[8][128];
  __shared__ float Bs[8][128];

  const int tid = threadIdx.x;
  const int bm = blockIdx.y;
  const int bn = blockIdx.x;

  const int lrow = tid >> 1;
  const int lcol = (tid & 1) << 2;
  const float* Ag = X + (size_t)(bm * 128 + lrow) * Iz + lcol;
  const float* Bg = Wih + (size_t)(bn * 128 + lrow) * Iz + lcol;

  const int tr = tid >> 4;
  const int tc = tid & 15;

  float acc[8][8];
#pragma unroll
  for (int i = 0; i < 8; i++)
#pragma unroll
    for (int j = 0; j < 8; j++) acc[i][j] = 0.f;

  for (int k0 = 0; k0 < Iz; k0 += 8) {
    float4 a4 = *reinterpret_cast<const float4*>(Ag + k0);
    float4 b4 = *reinterpret_cast<const float4*>(Bg + k0);
    As[lcol + 0][lrow] = a4.x;
    As[lcol + 1][lrow] = a4.y;
    As[lcol + 2][lrow] = a4.z;
    As[lcol + 3][lrow] = a4.w;
    Bs[lcol + 0][lrow] = b4.x;
    Bs[lcol + 1][lrow] = b4.y;
    Bs[lcol + 2][lrow] = b4.z;
    Bs[lcol + 3][lrow] = b4.w;
    __syncthreads();

#pragma unroll
    for (int k = 0; k < 8; k++) {
      float ra[8], rb[8];
      *reinterpret_cast<float4*>(ra) =
          *reinterpret_cast<const float4*>(&As[k][tr * 8]);
      *reinterpret_cast<float4*>(ra + 4) =
          *reinterpret_cast<const float4*>(&As[k][tr * 8 + 4]);
      *reinterpret_cast<float4*>(rb) =
          *reinterpret_cast<const float4*>(&Bs[k][tc * 8]);
      *reinterpret_cast<float4*>(rb + 4) =
          *reinterpret_cast<const float4*>(&Bs[k][tc * 8 + 4]);
#pragma unroll
      for (int i = 0; i < 8; i++)
#pragma unroll
        for (int j = 0; j < 8; j++) acc[i][j] += ra[i] * rb[j];
    }
    __syncthreads();
  }

  float bias[8];
#pragma unroll
  for (int j = 0; j < 8; j++) {
    int n = bn * 128 + tc * 8 + j;
    bias[j] = bih[n] + bhh[n];
  }

#pragma unroll
  for (int i = 0; i < 8; i++) {
    size_t row = (size_t)(bm * 128 + tr * 8 + i) * Hz;
    size_t col = (size_t)bn * 128 + tc * 8;
#pragma unroll
    for (int j = 0; j < 8; j += 4) {
      float4 v;
      v.x = acc[i][j + 0] + bias[j + 0];
      v.y = acc[i][j + 1] + bias[j + 1];
      v.z = acc[i][j + 2] + bias[j + 2];
      v.w = acc[i][j + 3] + bias[j + 3];
      *reinterpret_cast<float4*>(&g_pre[row + col + j]) = v;
    }
  }
}

// ---------------------------------------------------------------------------
// Phase 3: h_final[d,b,h] = out[b, S-4+d, h]
// ---------------------------------------------------------------------------
__global__ void final_state_kernel(const float* __restrict__ out,
                                   float* __restrict__ hf) {
  int idx = blockIdx.x * 256 + threadIdx.x;  // DZ*Bz*Hz = 262144
  int h = idx & (Hz - 1);
  int bd = idx >> 10;
  int b = bd & (Bz - 1);
  int d = bd >> 6;
  hf[idx] = out[((size_t)b * Sz + (Sz - DZ + d)) * Hz + h];
}

extern "C" void kernel_launch(void* const* d_in, const int* in_sizes, int n_in,
                              void* d_out, int out_size) {
  (void)in_sizes;
  (void)n_in;
  (void)out_size;
  const float* X = (const float*)d_in[0];    // [B,S,I]
  const float* hs = (const float*)d_in[1];   // [4,B,H]
  const float* Wih = (const float*)d_in[2];  // [H,I]
  const float* Whh = (const float*)d_in[3];  // [H,H]
  const float* bih = (const float*)d_in[4];  // [H]
  const float* bhh = (const float*)d_in[5];  // [H]

  float* out = (float*)d_out;              // [B,S,H]
  float* hf = out + (size_t)Bz * Sz * Hz;  // [4,B,H]

  pre_gemm_kernel<<<dim3(Hz / 128, (Bz * Sz) / 128), 256>>>(X, Wih, bih, bhh);

  rnn_persistent<<<NBLK, 512>>>(hs, Whh, out);

  final_state_kernel<<<(DZ * Bz * Hz) / 256, 256>>>(out, hf);
}